// round 13
// baseline (speedup 1.0000x reference)
#include <cuda_runtime.h>
#include <math.h>

#define N_NODES 100000
#define N_EDGES 1600000
#define F_INDIM 128
#define AGG 48
#define FC_H 192
#define NC 10
#define SLOPE 0.2f

// ---------------- scratch (static device globals; no allocation) ----------------
__device__ float  d_xl[N_NODES * AGG];
__device__ float  d_xr[N_NODES * AGG];
__device__ float  d_h [N_NODES * AGG];
__device__ float  d_g [AGG];
__device__ int    d_deg[N_NODES];
__device__ int    d_off[N_NODES + 1];
__device__ int    d_cur[N_NODES];
__device__ int    d_ctr[4];            // per-layer work-stealing counters
__device__ int    d_srcs[N_EDGES];     // src ids, CSR (dst-sorted) order
__device__ int    d_dsts[N_EDGES];     // dst ids, CSR order
__device__ float4 d_eas[N_EDGES];      // edge attrs, CSR order
__device__ float  d_el[N_EDGES];       // w_e = exp(attention logit), CSR order

// ---------------- CSR build ----------------
__global__ void k_zero() {
    int i = blockIdx.x * blockDim.x + threadIdx.x;
    if (i < N_NODES) d_deg[i] = 0;
    if (i < AGG)     d_g[i] = 0.f;
    if (i < 4)       d_ctr[i] = 0;
}

__global__ void k_count(const int* __restrict__ dst) {
    int e = blockIdx.x * blockDim.x + threadIdx.x;
    if (e < N_EDGES) atomicAdd(&d_deg[dst[e]], 1);
}

// single-block exclusive scan, int4-vectorized (25 chunk iterations)
__global__ void k_scan() {
    __shared__ int wsum[32];
    __shared__ int carry;
    int t = threadIdx.x, lane = t & 31, w = t >> 5;
    if (t == 0) carry = 0;
    __syncthreads();
    for (int base = 0; base < N_NODES; base += 4096) {
        int idx = base + t * 4;
        int4 v4 = make_int4(0, 0, 0, 0);
        if (idx < N_NODES) v4 = *(const int4*)&d_deg[idx];   // N_NODES % 4 == 0
        int s = v4.x + v4.y + v4.z + v4.w;
        int x = s;
        #pragma unroll
        for (int o = 1; o < 32; o <<= 1) {
            int y = __shfl_up_sync(0xffffffffu, x, o);
            if (lane >= o) x += y;
        }
        if (lane == 31) wsum[w] = x;
        __syncthreads();
        if (w == 0) {
            int ss = wsum[lane];
            #pragma unroll
            for (int o = 1; o < 32; o <<= 1) {
                int y = __shfl_up_sync(0xffffffffu, ss, o);
                if (lane >= o) ss += y;
            }
            wsum[lane] = ss;
        }
        __syncthreads();
        int incl = x + (w > 0 ? wsum[w - 1] : 0) + carry;
        if (idx < N_NODES) {
            int o0 = incl - s;
            int o1 = o0 + v4.x;
            int o2 = o1 + v4.y;
            int o3 = o2 + v4.z;
            d_off[idx] = o0;     d_cur[idx] = o0;
            d_off[idx + 1] = o1; d_cur[idx + 1] = o1;
            d_off[idx + 2] = o2; d_cur[idx + 2] = o2;
            d_off[idx + 3] = o3; d_cur[idx + 3] = o3;
        }
        __syncthreads();
        if (t == 1023) carry = incl;
        __syncthreads();
    }
    if (t == 0) d_off[N_NODES] = carry;
}

// scatter edges into CSR order, pre-gathering src, dst and edge attr
__global__ void k_scatter(const int* __restrict__ src, const int* __restrict__ dst,
                          const float4* __restrict__ ea) {
    int e = blockIdx.x * blockDim.x + threadIdx.x;
    if (e < N_EDGES) {
        int d = dst[e];
        int p = atomicAdd(&d_cur[d], 1);
        d_srcs[p] = src[e];
        d_dsts[p] = d;
        d_eas[p]  = ea[e];
    }
}

// ---------------- fused node-wise linears: xl = h@Wl.T+bl, xr = h@Wr.T+br ----------------
// Register-tiled: thread = 4 nodes x 4 channels. 240 active threads = 80 nodes/block.
__global__ void k_gemm2(const float* __restrict__ hin_ext, int use_h, int D,
                        const float* __restrict__ Wl, const float* __restrict__ bl,
                        const float* __restrict__ Wr, const float* __restrict__ br) {
    __shared__ float WsL[F_INDIM * AGG];  // transposed: Ws[k*48 + c]
    __shared__ float WsR[F_INDIM * AGG];
    const float* hin = use_h ? d_h : hin_ext;

    int t = threadIdx.x;
    int tot = D * AGG;
    for (int j = t; j < tot; j += blockDim.x) {
        int c = j / D, k = j % D;          // W row-major [AGG][D]
        WsL[k * AGG + c] = Wl[j];
        WsR[k * AGG + c] = Wr[j];
    }
    __syncthreads();
    if (t >= 240) return;

    int cg = t % 12;
    int grp = t / 12;
    int n0 = blockIdx.x * 80 + grp * 4;

    float4 bL = ((const float4*)bl)[cg];
    float4 bR = ((const float4*)br)[cg];
    float4 aL[4] = {bL, bL, bL, bL};
    float4 aR[4] = {bR, bR, bR, bR};

    const float* hp = hin + (size_t)n0 * D;

    for (int k = 0; k < D; k += 4) {
        float4 h4[4];
        #pragma unroll
        for (int nn = 0; nn < 4; nn++)
            h4[nn] = *(const float4*)(hp + nn * D + k);
        #pragma unroll
        for (int j = 0; j < 4; j++) {
            float4 wl = *(const float4*)&WsL[(k + j) * AGG + cg * 4];
            float4 wr = *(const float4*)&WsR[(k + j) * AGG + cg * 4];
            #pragma unroll
            for (int nn = 0; nn < 4; nn++) {
                float hv = (j == 0) ? h4[nn].x : (j == 1) ? h4[nn].y
                         : (j == 2) ? h4[nn].z : h4[nn].w;
                aL[nn].x = fmaf(hv, wl.x, aL[nn].x);
                aL[nn].y = fmaf(hv, wl.y, aL[nn].y);
                aL[nn].z = fmaf(hv, wl.z, aL[nn].z);
                aL[nn].w = fmaf(hv, wl.w, aL[nn].w);
                aR[nn].x = fmaf(hv, wr.x, aR[nn].x);
                aR[nn].y = fmaf(hv, wr.y, aR[nn].y);
                aR[nn].z = fmaf(hv, wr.z, aR[nn].z);
                aR[nn].w = fmaf(hv, wr.w, aR[nn].w);
            }
        }
    }
    #pragma unroll
    for (int nn = 0; nn < 4; nn++) {
        ((float4*)d_xl)[(n0 + nn) * 12 + cg] = aL[nn];
        ((float4*)d_xr)[(n0 + nn) * 12 + cg] = aR[nn];
    }
}

// ---------------- edge-parallel exp(logit) (CSR order) ----------------
// Warp = 8 edges; 4 lanes/edge, each lane covers 12 channels (3 float4 groups).
// Grid covers exactly N_EDGES. Full-warp lockstep; 2-shfl reduction per edge group.
// Writes w_e = exp(logit) -- valid in fp32 since logits are O(+-15) (glorot scale).
__global__ void k_logit(const float* __restrict__ We, const float* __restrict__ att) {
    __shared__ float sWe[AGG * 4];   // sWe[c*4+d]
    __shared__ float sAtt[AGG];
    int t = threadIdx.x;
    if (t < AGG * 4) sWe[t] = We[t];
    if (t < AGG)     sAtt[t] = att[t];
    __syncthreads();

    int gwarp = (blockIdx.x * blockDim.x + t) >> 5;
    int lane = t & 31;
    int g = lane >> 2, q = lane & 3;
    int i = gwarp * 8 + g;                  // always < N_EDGES (grid exact)

    int u = __ldg(&d_srcs[i]);
    int v = __ldg(&d_dsts[i]);
    float4 e4 = __ldg(&d_eas[i]);

    const float4* xlp = ((const float4*)d_xl) + u * 12 + q * 3;
    const float4* xrp = ((const float4*)d_xr) + v * 12 + q * 3;

    float part = 0.f;
    #pragma unroll
    for (int j = 0; j < 3; j++) {
        float4 xl4 = __ldg(xlp + j);
        float4 xr4 = __ldg(xrp + j);
        int cb = q * 12 + j * 4;
        float4 w0 = *(const float4*)&sWe[(cb + 0) * 4];
        float4 w1 = *(const float4*)&sWe[(cb + 1) * 4];
        float4 w2 = *(const float4*)&sWe[(cb + 2) * 4];
        float4 w3 = *(const float4*)&sWe[(cb + 3) * 4];
        float m0 = xl4.x + xr4.x + e4.x * w0.x + e4.y * w0.y + e4.z * w0.z + e4.w * w0.w;
        float m1 = xl4.y + xr4.y + e4.x * w1.x + e4.y * w1.y + e4.z * w1.z + e4.w * w1.w;
        float m2 = xl4.z + xr4.z + e4.x * w2.x + e4.y * w2.y + e4.z * w2.z + e4.w * w2.w;
        float m3 = xl4.w + xr4.w + e4.x * w3.x + e4.y * w3.y + e4.z * w3.z + e4.w * w3.w;
        part = fmaf(sAtt[cb + 0], fmaxf(m0, SLOPE * m0), part);
        part = fmaf(sAtt[cb + 1], fmaxf(m1, SLOPE * m1), part);
        part = fmaf(sAtt[cb + 2], fmaxf(m2, SLOPE * m2), part);
        part = fmaf(sAtt[cb + 3], fmaxf(m3, SLOPE * m3), part);
    }
    part += __shfl_xor_sync(0xffffffffu, part, 1);
    part += __shfl_xor_sync(0xffffffffu, part, 2);
    if (q == 0) d_el[i] = __expf(part);
}

// ---------------- node aggregation: work-stealing, pure gather-sum ----------------
// w_e precomputed -> per 4 edges: broadcast w + src loads, xl float4 gathers, FMAs.
// NO shuffles, NO exp in the loop; only loop-carried ops are 4-cycle adds.
// Half-warp per node (stride-2 edge split); predicated 4-edge unroll (w=0 for OOB).
__global__ void k_agg3(const float* __restrict__ bias, int layer, int fuse_readout) {
    __shared__ float sG[AGG];
    int t = threadIdx.x;
    if (t < AGG) sG[t] = 0.f;
    __syncthreads();

    int lane = t & 31;
    int half = lane >> 4, L = lane & 15;
    bool active = (L < 12);
    float4 z = make_float4(0, 0, 0, 0);
    float4 b4 = active ? __ldg(((const float4*)bias) + L) : z;
    float4 rsum = z;

    while (true) {
        int b = 0;
        if (lane == 0) b = atomicAdd(&d_ctr[layer], 8);
        b = __shfl_sync(0xffffffffu, b, 0);
        if (b >= N_NODES) break;
        int bend = min(b + 8, N_NODES);

        for (int v = b; v < bend; v++) {
            float den = 0.f;
            float4 acc = z;
            int beg = d_off[v], end = d_off[v + 1];

            for (int i = beg + half; i < end; i += 8) {
                #pragma unroll
                for (int k = 0; k < 4; k++) {
                    int ii = i + k * 2;
                    bool ok = ii < end;          // uniform within half
                    int j = ok ? ii : beg;
                    float w = ok ? __ldg(&d_el[j]) : 0.f;
                    int u = __ldg(&d_srcs[j]);
                    float4 x = active ? __ldg(((const float4*)d_xl) + u * 12 + L) : z;
                    den  += w;
                    acc.x += w * x.x;
                    acc.y += w * x.y;
                    acc.z += w * x.z;
                    acc.w += w * x.w;
                }
            }

            // reconverge warp, merge the two halves' sums (pairwise exchange)
            __syncwarp();
            den   += __shfl_xor_sync(0xffffffffu, den,   16);
            acc.x += __shfl_xor_sync(0xffffffffu, acc.x, 16);
            acc.y += __shfl_xor_sync(0xffffffffu, acc.y, 16);
            acc.z += __shfl_xor_sync(0xffffffffu, acc.z, 16);
            acc.w += __shfl_xor_sync(0xffffffffu, acc.w, 16);

            if (half == 0 && active) {
                float inv = 1.f / fmaxf(den, 1e-16f);
                float4 out;
                out.x = fmaxf(fmaf(acc.x, inv, b4.x), 0.f);
                out.y = fmaxf(fmaf(acc.y, inv, b4.y), 0.f);
                out.z = fmaxf(fmaf(acc.z, inv, b4.z), 0.f);
                out.w = fmaxf(fmaf(acc.w, inv, b4.w), 0.f);
                ((float4*)d_h)[v * 12 + L] = out;
                if (fuse_readout) {
                    rsum.x += out.x; rsum.y += out.y;
                    rsum.z += out.z; rsum.w += out.w;
                }
            }
        }
    }

    if (fuse_readout) {
        if (half == 0 && active) {
            int c4 = L * 4;
            atomicAdd(&sG[c4 + 0], rsum.x);
            atomicAdd(&sG[c4 + 1], rsum.y);
            atomicAdd(&sG[c4 + 2], rsum.z);
            atomicAdd(&sG[c4 + 3], rsum.w);
        }
        __syncthreads();
        if (t < AGG) atomicAdd(&d_g[t], sG[t]);
    }
}

// ---------------- MLP head + softmax ----------------
__global__ void k_mlp(const float* __restrict__ fc1w, const float* __restrict__ fc1b,
                      const float* __restrict__ fc2w, const float* __restrict__ fc2b,
                      float* __restrict__ out) {
    __shared__ float sg[AGG];
    __shared__ float sf[FC_H];
    __shared__ float sl[NC];
    int t = threadIdx.x;
    if (t < AGG) sg[t] = d_g[t];
    __syncthreads();
    if (t < FC_H) {
        float s = fc1b[t];
        #pragma unroll 8
        for (int k = 0; k < AGG; k++) s = fmaf(sg[k], fc1w[t * AGG + k], s);
        sf[t] = fmaxf(s, 0.f);
    }
    __syncthreads();
    if (t < NC) {
        float s = fc2b[t];
        for (int k = 0; k < FC_H; k++) s = fmaf(sf[k], fc2w[t * FC_H + k], s);
        sl[t] = s;
    }
    __syncthreads();
    if (t == 0) {
        float mx = sl[0];
        for (int i = 1; i < NC; i++) mx = fmaxf(mx, sl[i]);
        float sum = 0.f, ex[NC];
        for (int i = 0; i < NC; i++) { ex[i] = expf(sl[i] - mx); sum += ex[i]; }
        for (int i = 0; i < NC; i++) out[i] = ex[i] / sum;
    }
}

// ---------------- launch ----------------
extern "C" void kernel_launch(void* const* d_in, const int* in_sizes, int n_in,
                              void* d_out, int out_size) {
    const float* x   = (const float*)d_in[0];
    const int*   ei  = (const int*)d_in[1];
    const int*   src = ei;
    const int*   dst = ei + N_EDGES;
    const float* ea  = (const float*)d_in[2];

    const float *Wl[3], *bl[3], *Wr[3], *br[3], *We[3], *att[3], *bb[3];
    for (int l = 0; l < 3; l++) {
        int base = 3 + l * 7;
        Wl[l]  = (const float*)d_in[base + 0];
        bl[l]  = (const float*)d_in[base + 1];
        Wr[l]  = (const float*)d_in[base + 2];
        br[l]  = (const float*)d_in[base + 3];
        We[l]  = (const float*)d_in[base + 4];
        att[l] = (const float*)d_in[base + 5];
        bb[l]  = (const float*)d_in[base + 6];
    }
    const float* fc1w = (const float*)d_in[24];
    const float* fc1b = (const float*)d_in[25];
    const float* fc2w = (const float*)d_in[26];
    const float* fc2b = (const float*)d_in[27];
    float* out = (float*)d_out;

    k_zero   <<<(N_NODES + 255) / 256, 256>>>();
    k_count  <<<(N_EDGES + 255) / 256, 256>>>(dst);
    k_scan   <<<1, 1024>>>();
    k_scatter<<<(N_EDGES + 255) / 256, 256>>>(src, dst, (const float4*)ea);

    for (int l = 0; l < 3; l++) {
        int D = (l == 0) ? F_INDIM : AGG;
        k_gemm2<<<N_NODES / 80, 256>>>(x, (l > 0) ? 1 : 0, D, Wl[l], bl[l], Wr[l], br[l]);
        k_logit<<<N_EDGES / 64, 256>>>(We[l], att[l]);
        k_agg3 <<<1184, 256>>>(bb[l], l, (l == 2) ? 1 : 0);
    }

    k_mlp<<<1, 192>>>(fc1w, fc1b, fc2w, fc2b, out);
}

// round 14
// speedup vs baseline: 1.1734x; 1.1734x over previous
#include <cuda_runtime.h>
#include <math.h>

#define N_NODES 100000
#define N_EDGES 1600000
#define F_INDIM 128
#define AGG 48
#define FC_H 192
#define NC 10
#define SLOPE 0.2f

// ---------------- scratch (static device globals; no allocation) ----------------
__device__ float  d_xl[N_NODES * AGG];
__device__ float  d_xr[N_NODES * AGG];
__device__ float  d_h [N_NODES * AGG];
__device__ float  d_g [AGG];
__device__ int    d_deg[N_NODES];
__device__ int    d_off[N_NODES + 1];
__device__ int    d_cur[N_NODES];
__device__ int    d_ctr[4];            // per-layer work-stealing counters
__device__ int    d_srcs[N_EDGES];     // src ids, CSR (dst-sorted) order
__device__ float4 d_eas[N_EDGES];      // edge attrs, CSR order

// ---------------- CSR build ----------------
__global__ void k_zero() {
    int i = blockIdx.x * blockDim.x + threadIdx.x;
    if (i < N_NODES) d_deg[i] = 0;
    if (i < AGG)     d_g[i] = 0.f;
    if (i < 4)       d_ctr[i] = 0;
}

__global__ void k_count(const int* __restrict__ dst) {
    int e = blockIdx.x * blockDim.x + threadIdx.x;
    if (e < N_EDGES) atomicAdd(&d_deg[dst[e]], 1);
}

// single-block exclusive scan, int4-vectorized (25 chunk iterations)
__global__ void k_scan() {
    __shared__ int wsum[32];
    __shared__ int carry;
    int t = threadIdx.x, lane = t & 31, w = t >> 5;
    if (t == 0) carry = 0;
    __syncthreads();
    for (int base = 0; base < N_NODES; base += 4096) {
        int idx = base + t * 4;
        int4 v4 = make_int4(0, 0, 0, 0);
        if (idx < N_NODES) v4 = *(const int4*)&d_deg[idx];   // N_NODES % 4 == 0
        int s = v4.x + v4.y + v4.z + v4.w;
        int x = s;
        #pragma unroll
        for (int o = 1; o < 32; o <<= 1) {
            int y = __shfl_up_sync(0xffffffffu, x, o);
            if (lane >= o) x += y;
        }
        if (lane == 31) wsum[w] = x;
        __syncthreads();
        if (w == 0) {
            int ss = wsum[lane];
            #pragma unroll
            for (int o = 1; o < 32; o <<= 1) {
                int y = __shfl_up_sync(0xffffffffu, ss, o);
                if (lane >= o) ss += y;
            }
            wsum[lane] = ss;
        }
        __syncthreads();
        int incl = x + (w > 0 ? wsum[w - 1] : 0) + carry;
        if (idx < N_NODES) {
            int o0 = incl - s;
            int o1 = o0 + v4.x;
            int o2 = o1 + v4.y;
            int o3 = o2 + v4.z;
            d_off[idx] = o0;     d_cur[idx] = o0;
            d_off[idx + 1] = o1; d_cur[idx + 1] = o1;
            d_off[idx + 2] = o2; d_cur[idx + 2] = o2;
            d_off[idx + 3] = o3; d_cur[idx + 3] = o3;
        }
        __syncthreads();
        if (t == 1023) carry = incl;
        __syncthreads();
    }
    if (t == 0) d_off[N_NODES] = carry;
}

// scatter edges into CSR order, pre-gathering src id and edge attr
__global__ void k_scatter(const int* __restrict__ src, const int* __restrict__ dst,
                          const float4* __restrict__ ea) {
    int e = blockIdx.x * blockDim.x + threadIdx.x;
    if (e < N_EDGES) {
        int p = atomicAdd(&d_cur[dst[e]], 1);
        d_srcs[p] = src[e];
        d_eas[p]  = ea[e];
    }
}

// ---------------- fused node-wise linears: xl = h@Wl.T+bl, xr = h@Wr.T+br ----------------
// Register-tiled: thread = 4 nodes x 4 channels. 240 active threads = 80 nodes/block.
__global__ void k_gemm2(const float* __restrict__ hin_ext, int use_h, int D,
                        const float* __restrict__ Wl, const float* __restrict__ bl,
                        const float* __restrict__ Wr, const float* __restrict__ br) {
    __shared__ float WsL[F_INDIM * AGG];  // transposed: Ws[k*48 + c]
    __shared__ float WsR[F_INDIM * AGG];
    const float* hin = use_h ? d_h : hin_ext;

    int t = threadIdx.x;
    int tot = D * AGG;
    for (int j = t; j < tot; j += blockDim.x) {
        int c = j / D, k = j % D;          // W row-major [AGG][D]
        WsL[k * AGG + c] = Wl[j];
        WsR[k * AGG + c] = Wr[j];
    }
    __syncthreads();
    if (t >= 240) return;

    int cg = t % 12;
    int grp = t / 12;
    int n0 = blockIdx.x * 80 + grp * 4;

    float4 bL = ((const float4*)bl)[cg];
    float4 bR = ((const float4*)br)[cg];
    float4 aL[4] = {bL, bL, bL, bL};
    float4 aR[4] = {bR, bR, bR, bR};

    const float* hp = hin + (size_t)n0 * D;

    for (int k = 0; k < D; k += 4) {
        float4 h4[4];
        #pragma unroll
        for (int nn = 0; nn < 4; nn++)
            h4[nn] = *(const float4*)(hp + nn * D + k);
        #pragma unroll
        for (int j = 0; j < 4; j++) {
            float4 wl = *(const float4*)&WsL[(k + j) * AGG + cg * 4];
            float4 wr = *(const float4*)&WsR[(k + j) * AGG + cg * 4];
            #pragma unroll
            for (int nn = 0; nn < 4; nn++) {
                float hv = (j == 0) ? h4[nn].x : (j == 1) ? h4[nn].y
                         : (j == 2) ? h4[nn].z : h4[nn].w;
                aL[nn].x = fmaf(hv, wl.x, aL[nn].x);
                aL[nn].y = fmaf(hv, wl.y, aL[nn].y);
                aL[nn].z = fmaf(hv, wl.z, aL[nn].z);
                aL[nn].w = fmaf(hv, wl.w, aL[nn].w);
                aR[nn].x = fmaf(hv, wr.x, aR[nn].x);
                aR[nn].y = fmaf(hv, wr.y, aR[nn].y);
                aR[nn].z = fmaf(hv, wr.z, aR[nn].z);
                aR[nn].w = fmaf(hv, wr.w, aR[nn].w);
            }
        }
    }
    #pragma unroll
    for (int nn = 0; nn < 4; nn++) {
        ((float4*)d_xl)[(n0 + nn) * 12 + cg] = aL[nn];
        ((float4*)d_xr)[(n0 + nn) * 12 + cg] = aR[nn];
    }
}

// ---------------- GATv2 aggregation: work-stealing warps, 4 lanes/edge ----------------
// Warp processes one node at a time, fully converged (uniform loop bound):
//   lane = g*4 + q : g = edge slot (0..7, 8 edges per iteration), q = channel quarter
//   lane covers channels [q*12, q*12+12) = float4 groups q*3..q*3+2.
// Per edge: 2-level shfl reduction (xor 1,2) within the 4-lane group. No running max
// (den = sum exp, acc = sum exp*xl). OOB edge slots get w=0 (clamped index).
// Cross-slot merge once per node: 13 independent 3-level shfl chains (xor 4,8,16).
__global__ void k_agg(const float* __restrict__ We, const float* __restrict__ att,
                      const float* __restrict__ bias, int layer, int fuse_readout) {
    __shared__ float sG[AGG];
    int t = threadIdx.x;
    if (t < AGG) sG[t] = 0.f;
    __syncthreads();

    int lane = t & 31;
    int g = lane >> 2, q = lane & 3;
    float4 z = make_float4(0, 0, 0, 0);

    // per-lane weights: We rows for channels q*12..q*12+11, att groups q*3..q*3+2
    float4 W[12], A4[3], B4[3];
    #pragma unroll
    for (int c = 0; c < 12; c++) W[c] = __ldg(((const float4*)We) + q * 12 + c);
    #pragma unroll
    for (int c = 0; c < 3; c++) {
        A4[c] = __ldg(((const float4*)att) + q * 3 + c);
        B4[c] = __ldg(((const float4*)bias) + q * 3 + c);
    }

    float4 rsum[3] = {z, z, z};

    while (true) {
        int b = 0;
        if (lane == 0) b = atomicAdd(&d_ctr[layer], 8);
        b = __shfl_sync(0xffffffffu, b, 0);
        if (b >= N_NODES) break;
        int bend = min(b + 8, N_NODES);

        for (int v = b; v < bend; v++) {
            float4 xr[3];
            #pragma unroll
            for (int c = 0; c < 3; c++)
                xr[c] = ((const float4*)d_xr)[v * 12 + q * 3 + c];

            float den = 0.f;
            float4 acc[3] = {z, z, z};
            int beg = d_off[v], end = d_off[v + 1];

            for (int i0 = beg; i0 < end; i0 += 8) {   // uniform bound -> lockstep
                int i = i0 + g;
                bool ok = i < end;
                int j = ok ? i : beg;                  // clamped (beg < end here)
                int u = __ldg(&d_srcs[j]);
                float4 e4 = __ldg(&d_eas[j]);
                float4 x[3];
                #pragma unroll
                for (int c = 0; c < 3; c++)
                    x[c] = __ldg(((const float4*)d_xl) + u * 12 + q * 3 + c);

                float p = 0.f;
                #pragma unroll
                for (int c = 0; c < 3; c++) {
                    float4 w0 = W[c * 4 + 0], w1 = W[c * 4 + 1],
                           w2 = W[c * 4 + 2], w3 = W[c * 4 + 3];
                    float m0 = x[c].x + xr[c].x + e4.x * w0.x + e4.y * w0.y + e4.z * w0.z + e4.w * w0.w;
                    float m1 = x[c].y + xr[c].y + e4.x * w1.x + e4.y * w1.y + e4.z * w1.z + e4.w * w1.w;
                    float m2 = x[c].z + xr[c].z + e4.x * w2.x + e4.y * w2.y + e4.z * w2.z + e4.w * w2.w;
                    float m3 = x[c].w + xr[c].w + e4.x * w3.x + e4.y * w3.y + e4.z * w3.z + e4.w * w3.w;
                    p = fmaf(A4[c].x, fmaxf(m0, SLOPE * m0), p);
                    p = fmaf(A4[c].y, fmaxf(m1, SLOPE * m1), p);
                    p = fmaf(A4[c].z, fmaxf(m2, SLOPE * m2), p);
                    p = fmaf(A4[c].w, fmaxf(m3, SLOPE * m3), p);
                }
                // 2-level reduction within the 4-lane edge group
                p += __shfl_xor_sync(0xffffffffu, p, 1);
                p += __shfl_xor_sync(0xffffffffu, p, 2);
                float w = ok ? __expf(p) : 0.f;
                den += w;
                #pragma unroll
                for (int c = 0; c < 3; c++) {
                    acc[c].x += w * x[c].x;
                    acc[c].y += w * x[c].y;
                    acc[c].z += w * x[c].z;
                    acc[c].w += w * x[c].w;
                }
            }

            // merge across the 8 edge slots (lanes differing in g): xor 4, 8, 16
            #pragma unroll
            for (int o = 4; o <= 16; o <<= 1) {
                den += __shfl_xor_sync(0xffffffffu, den, o);
                #pragma unroll
                for (int c = 0; c < 3; c++) {
                    acc[c].x += __shfl_xor_sync(0xffffffffu, acc[c].x, o);
                    acc[c].y += __shfl_xor_sync(0xffffffffu, acc[c].y, o);
                    acc[c].z += __shfl_xor_sync(0xffffffffu, acc[c].z, o);
                    acc[c].w += __shfl_xor_sync(0xffffffffu, acc[c].w, o);
                }
            }

            if (g == 0) {   // lanes 0..3 write channels q*12..q*12+11
                float inv = 1.f / fmaxf(den, 1e-16f);
                #pragma unroll
                for (int c = 0; c < 3; c++) {
                    float4 out;
                    out.x = fmaxf(fmaf(acc[c].x, inv, B4[c].x), 0.f);
                    out.y = fmaxf(fmaf(acc[c].y, inv, B4[c].y), 0.f);
                    out.z = fmaxf(fmaf(acc[c].z, inv, B4[c].z), 0.f);
                    out.w = fmaxf(fmaf(acc[c].w, inv, B4[c].w), 0.f);
                    ((float4*)d_h)[v * 12 + q * 3 + c] = out;
                    if (fuse_readout) {
                        rsum[c].x += out.x; rsum[c].y += out.y;
                        rsum[c].z += out.z; rsum[c].w += out.w;
                    }
                }
            }
        }
    }

    if (fuse_readout) {
        if ((lane >> 2) == 0) {
            #pragma unroll
            for (int c = 0; c < 3; c++) {
                int cb = (q * 3 + c) * 4;
                atomicAdd(&sG[cb + 0], rsum[c].x);
                atomicAdd(&sG[cb + 1], rsum[c].y);
                atomicAdd(&sG[cb + 2], rsum[c].z);
                atomicAdd(&sG[cb + 3], rsum[c].w);
            }
        }
        __syncthreads();
        if (t < AGG) atomicAdd(&d_g[t], sG[t]);
    }
}

// ---------------- MLP head + softmax ----------------
__global__ void k_mlp(const float* __restrict__ fc1w, const float* __restrict__ fc1b,
                      const float* __restrict__ fc2w, const float* __restrict__ fc2b,
                      float* __restrict__ out) {
    __shared__ float sg[AGG];
    __shared__ float sf[FC_H];
    __shared__ float sl[NC];
    int t = threadIdx.x;
    if (t < AGG) sg[t] = d_g[t];
    __syncthreads();
    if (t < FC_H) {
        float s = fc1b[t];
        #pragma unroll 8
        for (int k = 0; k < AGG; k++) s = fmaf(sg[k], fc1w[t * AGG + k], s);
        sf[t] = fmaxf(s, 0.f);
    }
    __syncthreads();
    if (t < NC) {
        float s = fc2b[t];
        for (int k = 0; k < FC_H; k++) s = fmaf(sf[k], fc2w[t * FC_H + k], s);
        sl[t] = s;
    }
    __syncthreads();
    if (t == 0) {
        float mx = sl[0];
        for (int i = 1; i < NC; i++) mx = fmaxf(mx, sl[i]);
        float sum = 0.f, ex[NC];
        for (int i = 0; i < NC; i++) { ex[i] = expf(sl[i] - mx); sum += ex[i]; }
        for (int i = 0; i < NC; i++) out[i] = ex[i] / sum;
    }
}

// ---------------- launch ----------------
extern "C" void kernel_launch(void* const* d_in, const int* in_sizes, int n_in,
                              void* d_out, int out_size) {
    const float* x   = (const float*)d_in[0];
    const int*   ei  = (const int*)d_in[1];
    const int*   src = ei;
    const int*   dst = ei + N_EDGES;
    const float* ea  = (const float*)d_in[2];

    const float *Wl[3], *bl[3], *Wr[3], *br[3], *We[3], *att[3], *bb[3];
    for (int l = 0; l < 3; l++) {
        int base = 3 + l * 7;
        Wl[l]  = (const float*)d_in[base + 0];
        bl[l]  = (const float*)d_in[base + 1];
        Wr[l]  = (const float*)d_in[base + 2];
        br[l]  = (const float*)d_in[base + 3];
        We[l]  = (const float*)d_in[base + 4];
        att[l] = (const float*)d_in[base + 5];
        bb[l]  = (const float*)d_in[base + 6];
    }
    const float* fc1w = (const float*)d_in[24];
    const float* fc1b = (const float*)d_in[25];
    const float* fc2w = (const float*)d_in[26];
    const float* fc2b = (const float*)d_in[27];
    float* out = (float*)d_out;

    k_zero   <<<(N_NODES + 255) / 256, 256>>>();
    k_count  <<<(N_EDGES + 255) / 256, 256>>>(dst);
    k_scan   <<<1, 1024>>>();
    k_scatter<<<(N_EDGES + 255) / 256, 256>>>(src, dst, (const float4*)ea);

    for (int l = 0; l < 3; l++) {
        int D = (l == 0) ? F_INDIM : AGG;
        k_gemm2<<<N_NODES / 80, 256>>>(x, (l > 0) ? 1 : 0, D, Wl[l], bl[l], Wr[l], br[l]);
        k_agg  <<<2368, 128>>>(We[l], att[l], bb[l], l, (l == 2) ? 1 : 0);
    }

    k_mlp<<<1, 192>>>(fc1w, fc1b, fc2w, fc2b, out);
}